// round 5
// baseline (speedup 1.0000x reference)
#include <cuda_runtime.h>
#include <cuda_bf16.h>

// DiffLoss2: BCE-with-logits (mean) + argmax accuracy metrics.
//   B=65536 rows, A=8 attrs, V=128 vals. x:[B,1024] f32, s:[B,8] i32.
//   out[0] = mean(max(x,0) - x*onehot + log1p(exp(-|x|)))
//   out[1] = mean_b( all_a match ),  out[2] = mean_{b,a} match,
//   match = (argmax_v x[b,a,:] == s[b,a])  (value-equality; ties measure-zero)
//
// K1: single-wave persistent grid (444 blocks = 148 SMs x occ 3).
//     One warp = one row per iteration; 8 front-batched LDG.128 per lane
//     (MLP=8, 4KB/warp/row). Softplus with log-of-product fusion:
//       sum_j log1p(u_j) = log(prod_j (1+u_j)),  u_j = exp(-|x_j|)
//     -> 4 EX2 + 1 LG2 per float4 (5 MUFU vs 8). Value-only argmax,
//     SEL-tree target select (no spills), deferred warp-sum.
// K2: one block, deterministic double-precision final reduce.

#define NB    65536
#define NA    8
#define NBLK  444             // 148 SMs * 3 = exactly 1 wave at occ 3
#define NW    (NBLK * 8)      // 3552 warps

__device__ float g_loss[NW];
__device__ int   g_cnt[NW];
__device__ int   g_all[NW];

__global__ __launch_bounds__(256, 3)
void diffloss2_partial(const float* __restrict__ x, const int* __restrict__ s) {
    const int lane  = threadIdx.x & 31;
    const int gwarp = (blockIdx.x * blockDim.x + threadIdx.x) >> 5;

    const float4* __restrict__ x4 = reinterpret_cast<const float4*>(x);

    float lsum = 0.0f;
    int   cnt  = 0;
    int   all8 = 0;

    #pragma unroll 1
    for (int row = gwarp; row < NB; row += NW) {
        // Front-batched: 8 x LDG.128 per lane, contiguous 512B per warp each.
        float4 v[NA];
        #pragma unroll
        for (int a = 0; a < NA; ++a)
            v[a] = x4[(size_t)row * 256 + a * 32 + lane];

        int myS = 0;
        if (lane < NA) myS = __ldg(&s[row * NA + lane]);

        int rowmatch = 0;
        #pragma unroll
        for (int a = 0; a < NA; ++a) {
            const float x0 = v[a].x, x1 = v[a].y, x2 = v[a].z, x3 = v[a].w;

            // relu part
            lsum += fmaxf(x0, 0.0f) + fmaxf(x1, 0.0f)
                  + fmaxf(x2, 0.0f) + fmaxf(x3, 0.0f);

            // log1p part, fused: sum log1p(u_j) = log(prod (1+u_j)),
            // u_j = exp(-|x_j|) in (0,1] -> product in (1,16], no cancellation.
            const float u0 = __expf(-fabsf(x0));
            const float u1 = __expf(-fabsf(x1));
            const float u2 = __expf(-fabsf(x2));
            const float u3 = __expf(-fabsf(x3));
            lsum += __logf((1.0f + u0) * (1.0f + u1)
                         * (1.0f + u2) * (1.0f + u3));

            const int sv = __shfl_sync(0xffffffffu, myS, a);

            // This lane's candidate target logit: explicit SEL tree, stays
            // in registers (no LDL from runtime array indexing).
            const float t01  = (sv & 1) ? x1 : x0;
            const float t23  = (sv & 1) ? x3 : x2;
            const float tsel = (sv & 2) ? t23 : t01;

            // subtract target logit in the owning lane (replaces one-hot mul)
            if ((sv >> 2) == lane) lsum -= tsel;

            // warp max over the 128 values (values only)
            float m = fmaxf(fmaxf(x0, x1), fmaxf(x2, x3));
            #pragma unroll
            for (int off = 16; off > 0; off >>= 1)
                m = fmaxf(m, __shfl_xor_sync(0xffffffffu, m, off));

            // broadcast the target logit from its owning lane
            const float xt = __shfl_sync(0xffffffffu, tsel, sv >> 2);
            rowmatch += (xt >= m) ? 1 : 0;
        }
        cnt  += rowmatch;
        all8 += (rowmatch == NA) ? 1 : 0;
    }

    #pragma unroll
    for (int off = 16; off > 0; off >>= 1)
        lsum += __shfl_xor_sync(0xffffffffu, lsum, off);

    if (lane == 0) {
        g_loss[gwarp] = lsum;
        g_cnt[gwarp]  = cnt;
        g_all[gwarp]  = all8;
    }
}

__global__ __launch_bounds__(1024, 1)
void diffloss2_finalize(float* __restrict__ out) {
    const int tid = threadIdx.x;

    double s = 0.0;
    long long m = 0, al = 0;
    for (int j = tid; j < NW; j += 1024) {
        s  += (double)g_loss[j];
        m  += g_cnt[j];
        al += g_all[j];
    }

    __shared__ double    sd[1024];
    __shared__ long long si[1024];
    __shared__ long long sa[1024];
    sd[tid] = s; si[tid] = m; sa[tid] = al;
    __syncthreads();
    #pragma unroll
    for (int off = 512; off > 0; off >>= 1) {
        if (tid < off) {
            sd[tid] += sd[tid + off];
            si[tid] += si[tid + off];
            sa[tid] += sa[tid + off];
        }
        __syncthreads();
    }

    if (tid == 0) {
        out[0] = (float)(sd[0] / ((double)NB * (double)(NA * 128)));
        out[1] = (float)((double)sa[0] / (double)NB);
        out[2] = (float)((double)si[0] / ((double)NB * (double)NA));
    }
}

extern "C" void kernel_launch(void* const* d_in, const int* in_sizes, int n_in,
                              void* d_out, int out_size) {
    // Expected metadata order: sender_input [B*A] i32, receiver_output [B*1024] f32.
    const int*   s = (const int*)d_in[0];
    const float* x = (const float*)d_in[1];
    if (n_in >= 2 && in_sizes[0] == NB * NA * 128) {   // guard against reorder
        x = (const float*)d_in[0];
        s = (const int*)d_in[1];
    }
    float* out = (float*)d_out;

    diffloss2_partial<<<NBLK, 256>>>(x, s);
    diffloss2_finalize<<<1, 1024>>>(out);
}

// round 6
// speedup vs baseline: 1.0744x; 1.0744x over previous
#include <cuda_runtime.h>
#include <cuda_bf16.h>

// DiffLoss2: BCE-with-logits (mean) + argmax accuracy metrics. SINGLE kernel.
//   B=65536 rows, A=8 attrs, V=128 vals. x:[B,1024] f32, s:[B,8] i32.
//   out[0] = mean(max(x,0) - x*onehot + log1p(exp(-|x|)))
//   out[1] = mean_b( all_a match ),  out[2] = mean_{b,a} match
//
// Grid: 444 blocks (148 SMs x occ 3), one warp = one row per iteration,
// 8 front-batched LDG.128 per lane (MLP=8). Softplus via log-of-product
// fusion (4 EX2 + 1 LG2 per float4). Argmax via __reduce_max_sync on a
// monotone uint key + ballot (no 5-SHFL butterfly).
// Reduction: deterministic integer REDs (fixed-point loss, x 2^15) into
// __device__ globals; last block (threadfence+counter) writes out[0..2]
// and RESETS the accumulators so every graph replay starts clean
// (zero-init covers the first call).

#define NB    65536
#define NA    8
#define NBLK  444             // 148 SMs * 3 = exactly 1 wave at occ 3
#define NW    (NBLK * 8)
#define LSCALE 32768.0        // 2^15 fixed-point for the loss sum

__device__ long long          g_loss_fx;   // zero-init
__device__ int                g_cnt;
__device__ int                g_all;
__device__ unsigned int       g_ctr;

// Monotone key: float order == unsigned order (no NaNs in input).
__device__ __forceinline__ unsigned int fkey(float f) {
    unsigned int u = __float_as_uint(f);
    return ((int)u >= 0) ? (u ^ 0x80000000u) : ~u;
}

__global__ __launch_bounds__(256, 3)
void diffloss2_fused(const float* __restrict__ x, const int* __restrict__ s,
                     float* __restrict__ out) {
    const int lane  = threadIdx.x & 31;
    const int gwarp = (blockIdx.x * blockDim.x + threadIdx.x) >> 5;

    const float4* __restrict__ x4 = reinterpret_cast<const float4*>(x);

    float lsum = 0.0f;
    int   cnt  = 0;
    int   all8 = 0;

    #pragma unroll 1
    for (int row = gwarp; row < NB; row += NW) {
        // Front-batched: 8 x LDG.128 per lane (4KB/warp/row), coalesced.
        float4 v[NA];
        #pragma unroll
        for (int a = 0; a < NA; ++a)
            v[a] = x4[(size_t)row * 256 + a * 32 + lane];

        int myS = 0;
        if (lane < NA) myS = __ldg(&s[row * NA + lane]);

        int rowmatch = 0;
        #pragma unroll
        for (int a = 0; a < NA; ++a) {
            const float x0 = v[a].x, x1 = v[a].y, x2 = v[a].z, x3 = v[a].w;

            // relu part
            lsum += fmaxf(x0, 0.0f) + fmaxf(x1, 0.0f)
                  + fmaxf(x2, 0.0f) + fmaxf(x3, 0.0f);

            // sum_j log1p(u_j) = log(prod (1+u_j)), u_j = exp(-|x_j|) in (0,1]
            const float u0 = __expf(-fabsf(x0));
            const float u1 = __expf(-fabsf(x1));
            const float u2 = __expf(-fabsf(x2));
            const float u3 = __expf(-fabsf(x3));
            lsum += __logf((1.0f + u0) * (1.0f + u1)
                         * (1.0f + u2) * (1.0f + u3));

            const int sv = __shfl_sync(0xffffffffu, myS, a);

            // This lane's candidate target logit (SEL tree, registers only).
            const float t01  = (sv & 1) ? x1 : x0;
            const float t23  = (sv & 1) ? x3 : x2;
            const float tsel = (sv & 2) ? t23 : t01;

            const bool owner = ((sv >> 2) == lane);
            if (owner) lsum -= tsel;           // replaces the one-hot multiply

            // warp argmax via one REDUX on the monotone key
            const unsigned int lk =
                fkey(fmaxf(fmaxf(x0, x1), fmaxf(x2, x3)));
            const unsigned int mk = __reduce_max_sync(0xffffffffu, lk);

            // owner lane tests target==max locally; ballot shares the verdict
            const unsigned int bal =
                __ballot_sync(0xffffffffu, owner && (fkey(tsel) == mk));
            rowmatch += (bal != 0u) ? 1 : 0;
        }
        cnt  += rowmatch;
        all8 += (rowmatch == NA) ? 1 : 0;
    }

    // warp-sum the loss once
    #pragma unroll
    for (int off = 16; off > 0; off >>= 1)
        lsum += __shfl_xor_sync(0xffffffffu, lsum, off);

    // deterministic integer REDs (order-independent)
    if (lane == 0) {
        atomicAdd((unsigned long long*)&g_loss_fx,
                  (unsigned long long)__double2ll_rn((double)lsum * LSCALE));
        atomicAdd(&g_cnt, cnt);
        atomicAdd(&g_all, all8);
    }
    __syncthreads();

    // last block writes the outputs and resets state for the next replay
    if (threadIdx.x == 0) {
        __threadfence();
        const unsigned int old = atomicAdd(&g_ctr, 1u);
        if (old == NBLK - 1) {
            __threadfence();
            const long long lf = atomicAdd((unsigned long long*)&g_loss_fx, 0ull);
            const int       c  = atomicAdd(&g_cnt, 0);
            const int       al = atomicAdd(&g_all, 0);

            out[0] = (float)(((double)lf / LSCALE)
                             / ((double)NB * (double)(NA * 128)));
            out[1] = (float)((double)al / (double)NB);
            out[2] = (float)((double)c  / ((double)NB * (double)NA));

            // reset accumulators (graph replays reuse them)
            g_loss_fx = 0ll;
            g_cnt     = 0;
            g_all     = 0;
            __threadfence();
            g_ctr     = 0u;
        }
    }
}

extern "C" void kernel_launch(void* const* d_in, const int* in_sizes, int n_in,
                              void* d_out, int out_size) {
    // Expected metadata order: sender_input [B*A] i32, receiver_output [B*1024] f32.
    const int*   s = (const int*)d_in[0];
    const float* x = (const float*)d_in[1];
    if (n_in >= 2 && in_sizes[0] == NB * NA * 128) {   // guard against reorder
        x = (const float*)d_in[0];
        s = (const int*)d_in[1];
    }
    float* out = (float*)d_out;

    diffloss2_fused<<<NBLK, 256>>>(x, s, out);
}

// round 7
// speedup vs baseline: 1.0786x; 1.0039x over previous
#include <cuda_runtime.h>
#include <cuda_bf16.h>

// DiffLoss2: BCE-with-logits (mean) + argmax accuracy metrics. SINGLE kernel.
//   B=65536 rows, A=8 attrs, V=128 vals. x:[B,1024] f32, s:[B,8] i32.
//
// Grid: 444 blocks (148 SMs x occ 3), one warp = one row per iteration,
// 8 front-batched LDG.128 per lane (MLP=8). Softplus via log-of-product
// fusion (4 EX2 + 1 LG2 per float4).
//
// R7 change: targets loaded as two broadcast int4 (no SHFL), target logits
// re-loaded at warp-uniform addresses (L1-hit: the warp just fetched those
// lines) -> kills SEL tree, owner predication, fkey(tsel) and ballot.
// Per-attr match = (fkey(xt) == REDUX.MAX of lane keys), warp-uniform.
// Loss subtraction = one xt[] sum per row, lane-0 predicated.
//
// Reduction: deterministic fixed-point integer REDs (x 2^15); last block
// writes out[0..2] and resets accumulators for graph replays.

#define NB    65536
#define NA    8
#define NBLK  444             // 148 SMs * 3 = exactly 1 wave at occ 3
#define NW    (NBLK * 8)
#define LSCALE 32768.0        // 2^15 fixed-point for the loss sum

__device__ long long    g_loss_fx;   // zero-init
__device__ int          g_cnt;
__device__ int          g_all;
__device__ unsigned int g_ctr;

// Monotone key: float order == unsigned order (no NaNs in input).
// SHF + LOP3 after constant folding.
__device__ __forceinline__ unsigned int fkey(float f) {
    const unsigned int u = __float_as_uint(f);
    const unsigned int m = (unsigned int)((int)u >> 31) | 0x80000000u;
    return u ^ m;
}

__global__ __launch_bounds__(256, 3)
void diffloss2_fused(const float* __restrict__ x, const int* __restrict__ s,
                     float* __restrict__ out) {
    const int lane  = threadIdx.x & 31;
    const int gwarp = (blockIdx.x * blockDim.x + threadIdx.x) >> 5;

    const float4* __restrict__ x4 = reinterpret_cast<const float4*>(x);

    float lsum = 0.0f;
    int   cnt  = 0;
    int   all8 = 0;

    #pragma unroll 1
    for (int row = gwarp; row < NB; row += NW) {
        // Targets first (warp-uniform broadcast, 1 sector): all 8 in registers.
        const int4 s0 = __ldg((const int4*)(s + row * NA));
        const int4 s1 = __ldg((const int4*)(s + row * NA) + 1);
        const int sv[NA] = {s0.x, s0.y, s0.z, s0.w, s1.x, s1.y, s1.z, s1.w};

        // Front-batched row data: 8 x LDG.128 per lane (4KB/warp), coalesced.
        float4 v[NA];
        #pragma unroll
        for (int a = 0; a < NA; ++a)
            v[a] = x4[(size_t)row * 256 + a * 32 + lane];

        // Target logits: warp-uniform addresses, L1-hit (lines just fetched).
        const float* __restrict__ xrow = x + (size_t)row * 1024;
        float xt[NA];
        #pragma unroll
        for (int a = 0; a < NA; ++a)
            xt[a] = __ldg(xrow + a * 128 + sv[a]);

        int rowmatch = 0;
        #pragma unroll
        for (int a = 0; a < NA; ++a) {
            const float x0 = v[a].x, x1 = v[a].y, x2 = v[a].z, x3 = v[a].w;

            // relu part
            lsum += fmaxf(x0, 0.0f) + fmaxf(x1, 0.0f)
                  + fmaxf(x2, 0.0f) + fmaxf(x3, 0.0f);

            // sum_j log1p(u_j) = log(prod (1+u_j)), u_j = exp(-|x_j|) in (0,1]
            const float u0 = __expf(-fabsf(x0));
            const float u1 = __expf(-fabsf(x1));
            const float u2 = __expf(-fabsf(x2));
            const float u3 = __expf(-fabsf(x3));
            lsum += __logf((1.0f + u0) * (1.0f + u1)
                         * (1.0f + u2) * (1.0f + u3));

            // warp argmax: local 3 FMNMX -> monotone key -> one REDUX.MAX
            const unsigned int mk = __reduce_max_sync(
                0xffffffffu, fkey(fmaxf(fmaxf(x0, x1), fmaxf(x2, x3))));

            // match iff target logit equals the warp max (uniform compare)
            rowmatch += (fkey(xt[a]) == mk) ? 1 : 0;
        }

        // subtract all 8 target logits once (replaces the one-hot multiply)
        const float tsub = ((xt[0] + xt[1]) + (xt[2] + xt[3]))
                         + ((xt[4] + xt[5]) + (xt[6] + xt[7]));
        if (lane == 0) lsum -= tsub;

        cnt  += rowmatch;                    // warp-uniform
        all8 += (rowmatch == NA) ? 1 : 0;
    }

    // warp-sum the loss once
    #pragma unroll
    for (int off = 16; off > 0; off >>= 1)
        lsum += __shfl_xor_sync(0xffffffffu, lsum, off);

    // deterministic integer REDs (order-independent)
    if (lane == 0) {
        atomicAdd((unsigned long long*)&g_loss_fx,
                  (unsigned long long)__double2ll_rn((double)lsum * LSCALE));
        atomicAdd(&g_cnt, cnt);
        atomicAdd(&g_all, all8);
    }
    __syncthreads();

    // last block writes the outputs and resets state for the next replay
    if (threadIdx.x == 0) {
        __threadfence();
        const unsigned int old = atomicAdd(&g_ctr, 1u);
        if (old == NBLK - 1) {
            __threadfence();
            const long long lf = atomicAdd((unsigned long long*)&g_loss_fx, 0ull);
            const int       c  = atomicAdd(&g_cnt, 0);
            const int       al = atomicAdd(&g_all, 0);

            out[0] = (float)(((double)lf / LSCALE)
                             / ((double)NB * (double)(NA * 128)));
            out[1] = (float)((double)al / (double)NB);
            out[2] = (float)((double)c  / ((double)NB * (double)NA));

            g_loss_fx = 0ll;
            g_cnt     = 0;
            g_all     = 0;
            __threadfence();
            g_ctr     = 0u;
        }
    }
}

extern "C" void kernel_launch(void* const* d_in, const int* in_sizes, int n_in,
                              void* d_out, int out_size) {
    // Expected metadata order: sender_input [B*A] i32, receiver_output [B*1024] f32.
    const int*   s = (const int*)d_in[0];
    const float* x = (const float*)d_in[1];
    if (n_in >= 2 && in_sizes[0] == NB * NA * 128) {   // guard against reorder
        x = (const float*)d_in[0];
        s = (const int*)d_in[1];
    }
    float* out = (float*)d_out;

    diffloss2_fused<<<NBLK, 256>>>(x, s, out);
}